// round 4
// baseline (speedup 1.0000x reference)
#include <cuda_runtime.h>

#define NSRC 20000
#define NTAR 20000
#define NTOT (NSRC + NTAR)
#define G    32
#define G3   (G * G * G)
#define H    0.25f
#define INVH 4.0f
#define ORIG (-4.0f)
#define FLT_BIG 3.402823466e38f

// Scratch — device globals (zero-initialized at load; scan re-zeroes g_cnt each run)
__device__ int    g_cnt[2 * G3];      // combined histogram: [0,G3)=src, [G3,2G3)=tar
__device__ int    g_off[2 * G3 + 1];  // combined exclusive prefix (src offsets direct; tar shifted by NSRC)
__device__ int    g_fill[2 * G3];     // scatter cursors
__device__ int    g_pcell[NTOT];      // per-point cell id (combined)
__device__ float4 g_s4[NSRC];         // cell-sorted sources {x,y,z,0}
__device__ float4 g_t4[NTAR];         // cell-sorted targets {x,y,z, orig-index bits}
__device__ float  g_res[NTAR];        // per-ORIGINAL-target min d^2 (deterministic)

__device__ __forceinline__ int cellc(float v) {
    int c = (int)floorf((v - ORIG) * INVH);
    return min(max(c, 0), G - 1);
}

// K1: histogram src+tar into the combined grid.
__global__ void count_kernel(const float* __restrict__ src, const float* __restrict__ tar) {
    int i = blockIdx.x * blockDim.x + threadIdx.x;
    if (i >= NTOT) return;
    const float* p = (i < NSRC) ? (src + 3 * i) : (tar + 3 * (i - NSRC));
    int cid = (cellc(p[2]) * G + cellc(p[1])) * G + cellc(p[0]);
    if (i >= NSRC) cid += G3;
    g_pcell[i] = cid;
    atomicAdd(&g_cnt[cid], 1);
}

// K2: single-block exclusive scan of 65536 counts (1024 thr x 64 cells, two-pass
// read to keep registers low). Also writes g_fill and re-zeroes g_cnt.
__global__ __launch_bounds__(1024) void scan_kernel() {
    __shared__ int wsum[32];
    int tid = threadIdx.x;
    int base = tid * 64;

    int tot = 0;
    #pragma unroll
    for (int j = 0; j < 64; j += 4) {
        int4 q = *(const int4*)&g_cnt[base + j];
        tot += q.x + q.y + q.z + q.w;
    }

    int lane = tid & 31, wid = tid >> 5;
    int inc = tot;
    #pragma unroll
    for (int o = 1; o < 32; o <<= 1) {
        int y = __shfl_up_sync(0xffffffffu, inc, o);
        if (lane >= o) inc += y;
    }
    if (lane == 31) wsum[wid] = inc;
    __syncthreads();
    if (wid == 0) {
        int w = wsum[lane];
        #pragma unroll
        for (int o = 1; o < 32; o <<= 1) {
            int y = __shfl_up_sync(0xffffffffu, w, o);
            if (lane >= o) w += y;
        }
        wsum[lane] = w;
    }
    __syncthreads();

    int run = inc - tot + (wid ? wsum[wid - 1] : 0);
    #pragma unroll
    for (int j = 0; j < 64; j += 4) {
        int4 q = *(const int4*)&g_cnt[base + j];
        g_off[base + j + 0] = run; g_fill[base + j + 0] = run; run += q.x;
        g_off[base + j + 1] = run; g_fill[base + j + 1] = run; run += q.y;
        g_off[base + j + 2] = run; g_fill[base + j + 2] = run; run += q.z;
        *(int4*)&g_cnt[base + j] = make_int4(0, 0, 0, 0);   // reset for next replay
        g_off[base + j + 3] = run; g_fill[base + j + 3] = run; run += q.w;
    }
    if (tid == 1023) g_off[2 * G3] = run;
}

// K3: scatter src and tar into cell-sorted order. Within-cell order is
// nondeterministic, but per-target MIN is order-invariant and results are
// written back at original indices -> deterministic output.
__global__ void scatter_kernel(const float* __restrict__ src, const float* __restrict__ tar) {
    int i = blockIdx.x * blockDim.x + threadIdx.x;
    if (i >= NTOT) return;
    int cid = g_pcell[i];
    int pos = atomicAdd(&g_fill[cid], 1);
    if (i < NSRC) {
        g_s4[pos] = make_float4(src[3 * i + 0], src[3 * i + 1], src[3 * i + 2], 0.f);
    } else {
        int j = i - NSRC;
        g_t4[pos - NSRC] = make_float4(tar[3 * j + 0], tar[3 * j + 1], tar[3 * j + 2],
                                       __int_as_float(j));
    }
}

// K4: exact 1-NN via expanding Chebyshev shells. Targets are cell-sorted, so
// warps are coherent: shared cell ranges, shared point lines, aligned shells.
__global__ __launch_bounds__(128) void search_kernel() {
    int i = blockIdx.x * 128 + threadIdx.x;
    if (i >= NTAR) return;

    float4 t = g_t4[i];
    float tx = t.x, ty = t.y, tz = t.z;
    int cx = cellc(tx), cy = cellc(ty), cz = cellc(tz);

    float best = FLT_BIG;
    for (int r = 0; r < G; r++) {
        int za = max(cz - r, 0), zb = min(cz + r, G - 1);
        for (int z = za; z <= zb; z++) {
            bool zface = (z == cz - r) || (z == cz + r);
            int ya = max(cy - r, 0), yb = min(cy + r, G - 1);
            for (int y = ya; y <= yb; y++) {
                bool face = zface || (y == cy - r) || (y == cy + r);
                int rowbase = (z * G + y) * G;
                if (face) {
                    // full x-run is contiguous in the sorted array
                    int xa = max(cx - r, 0), xb = min(cx + r, G - 1);
                    int s = __ldg(&g_off[rowbase + xa]);
                    int e = __ldg(&g_off[rowbase + xb + 1]);
                    for (int p = s; p < e; p++) {
                        float4 q = __ldg(&g_s4[p]);
                        float dx = q.x - tx, dy = q.y - ty, dz = q.z - tz;
                        best = fminf(best, fmaf(dx, dx, fmaf(dy, dy, dz * dz)));
                    }
                } else {
                    #pragma unroll
                    for (int side = 0; side < 2; side++) {
                        int x = side ? (cx + r) : (cx - r);
                        if ((unsigned)x < G) {
                            int s = __ldg(&g_off[rowbase + x]);
                            int e = __ldg(&g_off[rowbase + x + 1]);
                            for (int p = s; p < e; p++) {
                                float4 q = __ldg(&g_s4[p]);
                                float dx = q.x - tx, dy = q.y - ty, dz = q.z - tz;
                                best = fminf(best, fmaf(dx, dx, fmaf(dy, dy, dz * dz)));
                            }
                        }
                    }
                }
            }
        }
        float bnd = (float)r * H;
        if (best <= bnd * bnd) break;   // every unscanned cell is >= r*H away
    }

    g_res[__float_as_int(t.w)] = best;  // deterministic slot (original index)
}

// K5: deterministic fixed-order sum of g_res, * 0.5.
__global__ __launch_bounds__(1024) void final_kernel(float* __restrict__ out) {
    int tid = threadIdx.x;
    float s = 0.f;
    for (int i = tid; i < NTAR; i += 1024)   // fixed order per thread
        s += g_res[i];

    __shared__ float ws[32];
    int lane = tid & 31, wid = tid >> 5;
    for (int off = 16; off; off >>= 1)
        s += __shfl_down_sync(0xffffffffu, s, off);
    if (lane == 0) ws[wid] = s;
    __syncthreads();
    if (tid == 0) {
        float v = 0.f;
        #pragma unroll
        for (int w = 0; w < 32; w++) v += ws[w];   // fixed order
        out[0] = 0.5f * v;
    }
}

extern "C" void kernel_launch(void* const* d_in, const int* in_sizes, int n_in,
                              void* d_out, int out_size) {
    const float* src = (const float*)d_in[0];   // [20000, 3] fp32
    const float* tar = (const float*)d_in[1];   // [20000, 3] fp32
    float* out = (float*)d_out;                 // scalar fp32

    count_kernel<<<(NTOT + 255) / 256, 256>>>(src, tar);
    scan_kernel<<<1, 1024>>>();
    scatter_kernel<<<(NTOT + 255) / 256, 256>>>(src, tar);
    search_kernel<<<(NTAR + 127) / 128, 128>>>();
    final_kernel<<<1, 1024>>>(out);
}

// round 5
// speedup vs baseline: 1.1378x; 1.1378x over previous
#include <cuda_runtime.h>

#define NSRC 20000
#define NTAR 20000
#define NTOT (NSRC + NTAR)
#define G    32
#define G3   (G * G * G)
#define H    0.25f
#define INVH 4.0f
#define ORIG (-4.0f)
#define FLT_BIG 3.402823466e38f
#define NBLK 148
#define NT   1024
#define NWARPS (NBLK * (NT / 32))      // 4736 warps

// Scratch — device globals (zero-initialized at load; scan re-zeroes g_cnt each run)
__device__ int    g_cnt[2 * G3];       // combined histogram: [0,G3)=src, [G3,2G3)=tar
__device__ int    g_off[2 * G3 + 1];   // combined exclusive prefix
__device__ int    g_fill[2 * G3];      // scatter cursors
__device__ int    g_pcell[NTOT];       // per-point cell id
__device__ float4 g_s4[NSRC];          // cell-sorted sources
__device__ float4 g_t4[NTAR];          // cell-sorted targets {x,y,z, orig idx}
__device__ float  g_res[NTAR];         // per-ORIGINAL-target min d^2 (deterministic)
__device__ float  g_bsum[NBLK];        // per-block partial sums
__device__ unsigned          g_bar_cnt;   // barrier arrivals (self-resetting)
__device__ volatile unsigned g_bar_gen;   // barrier generation (monotonic)

__device__ __forceinline__ int cellc(float v) {
    int c = (int)floorf((v - ORIG) * INVH);
    return min(max(c, 0), G - 1);
}

// Grid barrier: 148 blocks are all resident (1 block/SM), so spinning is safe.
__device__ __forceinline__ void gbar() {
    __syncthreads();
    if (threadIdx.x == 0) {
        __threadfence();
        unsigned gen = g_bar_gen;
        if (atomicAdd(&g_bar_cnt, 1u) == NBLK - 1) {
            g_bar_cnt = 0;
            __threadfence();
            g_bar_gen = gen + 1;
        } else {
            while (g_bar_gen == gen) __nanosleep(32);
            __threadfence();
        }
    }
    __syncthreads();
}

// Scan one contiguous x-run of cells: lanes stride its points, fold into best.
__device__ __forceinline__ void scan_run(int rowbase, int xa, int xb, int lane,
                                         float tx, float ty, float tz, float& best) {
    int s = __ldg(&g_off[rowbase + xa]);       // uniform -> broadcast
    int e = __ldg(&g_off[rowbase + xb + 1]);
    for (int p = s + lane; p < e; p += 32) {
        float4 q = __ldg(&g_s4[p]);            // coalesced
        float dx = q.x - tx, dy = q.y - ty, dz = q.z - tz;
        best = fminf(best, fmaf(dx, dx, fmaf(dy, dy, dz * dz)));
    }
}

__global__ __launch_bounds__(NT, 1) void fused_kernel(const float* __restrict__ src,
                                                      const float* __restrict__ tar,
                                                      float* __restrict__ out) {
    __shared__ int   s_wsum[32];
    __shared__ float s_red[32];
    int tid  = threadIdx.x;
    int gid  = blockIdx.x * NT + tid;
    int lane = tid & 31;
    int wid  = tid >> 5;

    // ---- Phase 0: histogram src+tar into combined grid ----
    if (gid < NTOT) {
        const float* p = (gid < NSRC) ? (src + 3 * gid) : (tar + 3 * (gid - NSRC));
        int cid = (cellc(p[2]) * G + cellc(p[1])) * G + cellc(p[0]);
        if (gid >= NSRC) cid += G3;
        g_pcell[gid] = cid;
        atomicAdd(&g_cnt[cid], 1);
    }
    gbar();

    // ---- Phase 1: block 0 scans all 65536 counts (others wait) ----
    if (blockIdx.x == 0) {
        int base = tid * 64;
        int tot = 0;
        #pragma unroll
        for (int j = 0; j < 64; j += 4) {
            int4 q = *(const int4*)&g_cnt[base + j];
            tot += q.x + q.y + q.z + q.w;
        }
        int inc = tot;
        #pragma unroll
        for (int o = 1; o < 32; o <<= 1) {
            int y = __shfl_up_sync(0xffffffffu, inc, o);
            if (lane >= o) inc += y;
        }
        if (lane == 31) s_wsum[wid] = inc;
        __syncthreads();
        if (wid == 0) {
            int w = s_wsum[lane];
            #pragma unroll
            for (int o = 1; o < 32; o <<= 1) {
                int y = __shfl_up_sync(0xffffffffu, w, o);
                if (lane >= o) w += y;
            }
            s_wsum[lane] = w;
        }
        __syncthreads();
        int run = inc - tot + (wid ? s_wsum[wid - 1] : 0);
        #pragma unroll
        for (int j = 0; j < 64; j += 4) {
            int4 q = *(const int4*)&g_cnt[base + j];
            g_off[base + j + 0] = run; g_fill[base + j + 0] = run; run += q.x;
            g_off[base + j + 1] = run; g_fill[base + j + 1] = run; run += q.y;
            g_off[base + j + 2] = run; g_fill[base + j + 2] = run; run += q.z;
            g_off[base + j + 3] = run; g_fill[base + j + 3] = run; run += q.w;
            *(int4*)&g_cnt[base + j] = make_int4(0, 0, 0, 0);   // reset for replay
        }
        if (tid == NT - 1) g_off[2 * G3] = run;
    }
    gbar();

    // ---- Phase 2: scatter into cell-sorted order ----
    // Within-cell order is racy, but per-target MIN is order-invariant and the
    // result lands at the original index -> deterministic output.
    if (gid < NTOT) {
        int cid = g_pcell[gid];
        int pos = atomicAdd(&g_fill[cid], 1);
        if (gid < NSRC) {
            g_s4[pos] = make_float4(src[3 * gid], src[3 * gid + 1], src[3 * gid + 2], 0.f);
        } else {
            int j = gid - NSRC;
            g_t4[pos - NSRC] = make_float4(tar[3 * j], tar[3 * j + 1], tar[3 * j + 2],
                                           __int_as_float(j));
        }
    }
    gbar();

    // ---- Phase 3: warp-per-target exact 1-NN (expanding Chebyshev shells) ----
    int gw = blockIdx.x * (NT / 32) + wid;
    for (int ti = gw; ti < NTAR; ti += NWARPS) {
        float4 t = g_t4[ti];
        float tx = t.x, ty = t.y, tz = t.z;
        int cx = cellc(tx), cy = cellc(ty), cz = cellc(tz);
        float best = FLT_BIG;

        // initial 3x3x3 cube (covers r<=1)
        {
            int za = max(cz - 1, 0), zb = min(cz + 1, G - 1);
            int ya = max(cy - 1, 0), yb = min(cy + 1, G - 1);
            int xa = max(cx - 1, 0), xb = min(cx + 1, G - 1);
            for (int z = za; z <= zb; z++)
                for (int y = ya; y <= yb; y++)
                    scan_run((z * G + y) * G, xa, xb, lane, tx, ty, tz, best);
        }
        float bw = best;
        #pragma unroll
        for (int o = 16; o; o >>= 1) bw = fminf(bw, __shfl_xor_sync(0xffffffffu, bw, o));

        int r = 2;
        // After scanning the full cube of radius r-1, any unscanned point is
        // >= (r-1)*H away (clamped points are only farther). Exact early exit.
        while (r < G && bw > ((float)(r - 1) * H) * ((float)(r - 1) * H)) {
            int xa = max(cx - r, 0), xb = min(cx + r, G - 1);
            #pragma unroll
            for (int zs = 0; zs < 2; zs++) {
                int z = cz + (zs ? r : -r);
                if ((unsigned)z < G) {
                    int ya = max(cy - r, 0), yb = min(cy + r, G - 1);
                    for (int y = ya; y <= yb; y++)
                        scan_run((z * G + y) * G, xa, xb, lane, tx, ty, tz, best);
                }
            }
            int za = max(cz - r + 1, 0), zb = min(cz + r - 1, G - 1);
            for (int z = za; z <= zb; z++) {
                #pragma unroll
                for (int ys = 0; ys < 2; ys++) {
                    int y = cy + (ys ? r : -r);
                    if ((unsigned)y < G)
                        scan_run((z * G + y) * G, xa, xb, lane, tx, ty, tz, best);
                }
                int ya2 = max(cy - r + 1, 0), yb2 = min(cy + r - 1, G - 1);
                for (int y = ya2; y <= yb2; y++) {
                    int rb = (z * G + y) * G;
                    if (cx - r >= 0) scan_run(rb, cx - r, cx - r, lane, tx, ty, tz, best);
                    if (cx + r < G)  scan_run(rb, cx + r, cx + r, lane, tx, ty, tz, best);
                }
            }
            bw = best;
            #pragma unroll
            for (int o = 16; o; o >>= 1) bw = fminf(bw, __shfl_xor_sync(0xffffffffu, bw, o));
            r++;
        }
        if (lane == 0) g_res[__float_as_int(t.w)] = bw;
    }
    gbar();

    // ---- Phase 4: deterministic fixed-order reduction ----
    {
        float v = (gid < NTAR) ? g_res[gid] : 0.f;
        #pragma unroll
        for (int o = 16; o; o >>= 1) v += __shfl_down_sync(0xffffffffu, v, o);
        if (lane == 0) s_red[wid] = v;
        __syncthreads();
        if (wid == 0) {
            float u = s_red[lane];
            #pragma unroll
            for (int o = 16; o; o >>= 1) u += __shfl_down_sync(0xffffffffu, u, o);
            if (lane == 0) g_bsum[blockIdx.x] = u;
        }
    }
    gbar();
    if (blockIdx.x == 0 && wid == 0) {
        float v = 0.f;
        for (int i = lane; i < NBLK; i += 32) v += g_bsum[i];   // fixed per-lane order
        #pragma unroll
        for (int o = 16; o; o >>= 1) v += __shfl_down_sync(0xffffffffu, v, o);
        if (lane == 0) out[0] = 0.5f * v;
    }
}

extern "C" void kernel_launch(void* const* d_in, const int* in_sizes, int n_in,
                              void* d_out, int out_size) {
    const float* src = (const float*)d_in[0];   // [20000, 3] fp32
    const float* tar = (const float*)d_in[1];   // [20000, 3] fp32
    float* out = (float*)d_out;                 // scalar fp32

    fused_kernel<<<NBLK, NT>>>(src, tar, out);
}

// round 6
// speedup vs baseline: 2.8633x; 2.5165x over previous
#include <cuda_runtime.h>

#define NSRC 20000
#define NTAR 20000
#define GRID     148
#define NTHREADS 256          // 8 warps = 2/SMSP
#define TPL      8            // targets per lane
#define TPB      (NTHREADS * TPL)   // 2048 targets per group
#define NGROUP   10           // ceil(20000/2048)
#define CHUNK    200          // sources per tile (6.4 KB)
#define NCHUNK   100
#define NUNITS   (NGROUP * NCHUNK)  // 1000
#define FLT_BIG  3.402823466e38f
#define INF_KEY  0x7F800000   // +inf bits (positive -> key == bits)

// Device-global scratch (no allocation allowed)
__device__ float g_src8[NSRC * 8];   // per src: {x,x,y,y,z,z,w,w}, w=||s||^2
__device__ int   g_pmk[NTAR];        // per-target min key (order-flipped float bits)
__device__ float g_gsum[20];         // finish block partials
__device__ unsigned g_ticket;        // last-block counter (self-resetting)

union F2U { unsigned long long u; float2 f; };

__device__ __forceinline__ unsigned long long pk(float lo, float hi) {
    F2U t; t.f = make_float2(lo, hi); return t.u;
}
__device__ __forceinline__ F2U fma2(unsigned long long a, unsigned long long b,
                                    unsigned long long c) {
    F2U d;
    asm("fma.rn.f32x2 %0, %1, %2, %3;" : "=l"(d.u) : "l"(a), "l"(b), "l"(c));
    return d;
}
// order-preserving float->int key (involution)
__device__ __forceinline__ int fkey(float f) {
    int b = __float_as_int(f);
    return b >= 0 ? b : (b ^ 0x7FFFFFFF);
}

// K1: build duplicated-packed sources + reset per-target min keys.
__global__ void prep_kernel(const float* __restrict__ src) {
    int i = blockIdx.x * blockDim.x + threadIdx.x;
    if (i < NTAR) g_pmk[i] = INF_KEY;
    if (i < NSRC) {
        float x = src[3 * i + 0];
        float y = src[3 * i + 1];
        float z = src[3 * i + 2];
        float w = x * x + y * y + z * z;
        float4* p = (float4*)g_src8;
        p[2 * i + 0] = make_float4(x, x, y, y);
        p[2 * i + 1] = make_float4(z, z, w, w);
    }
}

// K2: packed pairwise min, v = ||s||^2 - 2 s.t  (||t||^2 added in finish).
__global__ __launch_bounds__(NTHREADS, 1) void nn_kernel(const float* __restrict__ tar) {
    __shared__ ulonglong2 sh[2 * CHUNK];   // sh[2j]=(xx,yy), sh[2j+1]=(zz,ww)

    for (int u = blockIdx.x; u < NUNITS; u += GRID) {
        int g = u / NCHUNK;
        int c = u % NCHUNK;

        // 8 targets per lane (k-strided, coalesced), scaled by -2, packed in pairs.
        unsigned long long txp[4], typ[4], tzp[4];
        #pragma unroll
        for (int h = 0; h < 4; h++) {
            float ax = 0.f, ay = 0.f, az = 0.f, bx = 0.f, by = 0.f, bz = 0.f;
            int t0 = g * TPB + (2 * h) * NTHREADS + threadIdx.x;
            int t1 = t0 + NTHREADS;
            if (t0 < NTAR) { ax = -2.f * tar[3*t0]; ay = -2.f * tar[3*t0+1]; az = -2.f * tar[3*t0+2]; }
            if (t1 < NTAR) { bx = -2.f * tar[3*t1]; by = -2.f * tar[3*t1+1]; bz = -2.f * tar[3*t1+2]; }
            txp[h] = pk(ax, bx); typ[h] = pk(ay, by); tzp[h] = pk(az, bz);
        }

        __syncthreads();   // guard tile reuse
        {
            const float4* gs = (const float4*)g_src8 + (size_t)c * (2 * CHUNK);
            float4* shf = (float4*)sh;
            for (int j = threadIdx.x; j < 2 * CHUNK; j += NTHREADS)
                shf[j] = gs[j];
        }
        __syncthreads();

        float m[8];
        #pragma unroll
        for (int k = 0; k < 8; k++) m[k] = FLT_BIG;

        #pragma unroll 5
        for (int j = 0; j < CHUNK; j++) {
            ulonglong2 q = sh[2 * j];        // (x,x), (y,y)
            ulonglong2 r = sh[2 * j + 1];    // (z,z), (w,w)
            #pragma unroll
            for (int h = 0; h < 4; h++) {
                F2U v = fma2(q.x, txp[h], r.y);
                v = fma2(q.y, typ[h], v.u);
                v = fma2(r.x, tzp[h], v.u);
                m[2 * h]     = fminf(m[2 * h],     v.f.x);   // register-pair halves: no MOV
                m[2 * h + 1] = fminf(m[2 * h + 1], v.f.y);
            }
        }

        #pragma unroll
        for (int k = 0; k < 8; k++) {
            int t = g * TPB + k * NTHREADS + threadIdx.x;
            if (t < NTAR) atomicMin(&g_pmk[t], fkey(m[k]));   // min: order-invariant
        }
    }
}

// K3: decode keys, add ||t||^2, reduce; last block does the fixed-order final sum.
__global__ __launch_bounds__(1024) void finish_kernel(const float* __restrict__ tar,
                                                      float* __restrict__ out) {
    int i = blockIdx.x * 1024 + threadIdx.x;
    float contrib = 0.f;
    if (i < NTAR) {
        int k = g_pmk[i];
        float v = __int_as_float(k >= 0 ? k : (k ^ 0x7FFFFFFF));
        float x = tar[3 * i], y = tar[3 * i + 1], z = tar[3 * i + 2];
        contrib = v + x * x + y * y + z * z;   // = min ||s-t||^2
    }

    __shared__ float ws[32];
    int lane = threadIdx.x & 31, wid = threadIdx.x >> 5;
    for (int o = 16; o; o >>= 1) contrib += __shfl_down_sync(0xffffffffu, contrib, o);
    if (lane == 0) ws[wid] = contrib;
    __syncthreads();
    if (wid == 0) {
        float v = ws[lane];
        for (int o = 16; o; o >>= 1) v += __shfl_down_sync(0xffffffffu, v, o);
        if (lane == 0) {
            g_gsum[blockIdx.x] = v;
            __threadfence();
            unsigned tick = atomicAdd(&g_ticket, 1u);
            if (tick == gridDim.x - 1) {           // last block: fixed-order final sum
                float s = 0.f;
                #pragma unroll
                for (int b = 0; b < 20; b++) s += g_gsum[b];
                out[0] = 0.5f * s;
                g_ticket = 0;                       // reset for next graph replay
            }
        }
    }
}

extern "C" void kernel_launch(void* const* d_in, const int* in_sizes, int n_in,
                              void* d_out, int out_size) {
    const float* src = (const float*)d_in[0];   // [20000, 3] fp32
    const float* tar = (const float*)d_in[1];   // [20000, 3] fp32
    float* out = (float*)d_out;                 // scalar fp32

    prep_kernel<<<(NTAR + 255) / 256, 256>>>(src);
    nn_kernel<<<GRID, NTHREADS>>>(tar);
    finish_kernel<<<20, 1024>>>(tar, out);
}

// round 7
// speedup vs baseline: 3.3529x; 1.1710x over previous
#include <cuda_runtime.h>

#define NSRC 20000
#define NTAR 20000
#define NTOT (NSRC + NTAR)
#define NBLK 148
#define NT   256
#define GTH  (NBLK * NT)
#define NBIN 2048
#define ZMINV (-4.0f)
#define BINW (8.0f / NBIN)
#define INVBINW (NBIN / 8.0f)
#define NS   16
#define SLABQ (NSRC / NS)                  // 1250
#define TPL  4
#define TPG  (NT * TPL)                    // 1024 targets per group
#define NGRP ((NTAR + TPG - 1) / TPG)      // 20
#define TILE 256
#define NST  ((NSRC + TILE - 1) / TILE)    // 79
#define FLT_BIG 3.402823466e38f
#define INF_KEY 0x7F800000

// ---- device-global scratch (no allocation allowed) ----
__device__ int    g_histS[NBIN];
__device__ int    g_histT[NBIN];
__device__ int    g_lut[NBIN];
__device__ int    g_bndbin[NS + 1];
__device__ float  g_edgeZ[NS + 1];
__device__ int    g_soff[NS + 1];
__device__ int    g_sfill[NS];
__device__ int    g_toff[NS + 1];
__device__ int    g_tfill[NS];
__device__ float  g_s8[NSRC * 8];     // slab-sorted, packed {x,x,y,y,z,z,w,w}
__device__ float4 g_t4[NTAR];         // slab-sorted targets {x,y,z,||t||^2}
__device__ int    g_pmk[NTAR];        // per-sorted-target min key
__device__ int    g_gw[NGRP][2];      // per-group src window [beg,end)
__device__ float  g_gz[NGRP][2];      // per-group window z-edges
__device__ int    g_upref[NGRP + 1];  // unit prefix (tiles per group)
__device__ int    g_nfail;
__device__ int    g_flist[NTAR];
__device__ float  g_resF[NTAR];       // fallback contribs at sorted idx (0 else)
__device__ float  g_bsum[NBLK];
__device__ float  g_bsum2[NBLK];
__device__ unsigned          g_bar_cnt;
__device__ volatile unsigned g_bar_gen;

union F2U { unsigned long long u; float2 f; };
__device__ __forceinline__ unsigned long long pk(float lo, float hi) {
    F2U t; t.f = make_float2(lo, hi); return t.u;
}
__device__ __forceinline__ F2U fma2(unsigned long long a, unsigned long long b,
                                    unsigned long long c) {
    F2U d;
    asm("fma.rn.f32x2 %0, %1, %2, %3;" : "=l"(d.u) : "l"(a), "l"(b), "l"(c));
    return d;
}
__device__ __forceinline__ int fkey(float f) {       // order-preserving involution
    int b = __float_as_int(f);
    return b >= 0 ? b : (b ^ 0x7FFFFFFF);
}
__device__ __forceinline__ float fdec(int k) {
    return __int_as_float(k >= 0 ? k : (k ^ 0x7FFFFFFF));
}
__device__ __forceinline__ int finebin(float z) {
    int b = (int)floorf((z - ZMINV) * INVBINW);
    return min(max(b, 0), NBIN - 1);
}

// Grid barrier: 148 blocks, 1 per SM, all resident -> spinning is safe.
__device__ __forceinline__ void gbar() {
    __threadfence();
    __syncthreads();
    if (threadIdx.x == 0) {
        unsigned gen = g_bar_gen;
        if (atomicAdd(&g_bar_cnt, 1u) == NBLK - 1) {
            g_bar_cnt = 0;
            __threadfence();
            g_bar_gen = gen + 1;
        } else {
            while (g_bar_gen == gen) __nanosleep(64);
            __threadfence();
        }
    }
    __syncthreads();
}

// Block-0 inclusive scan of a 2048-int histogram into s_cum.
__device__ void scan2048(const int* hist, int* s_cum, int* s_ws) {
    int tid = threadIdx.x;
    int base = tid * 8;
    int v[8]; int tot = 0;
    #pragma unroll
    for (int j = 0; j < 8; j++) { v[j] = hist[base + j]; tot += v[j]; }
    int lane = tid & 31, wid = tid >> 5;
    int inc = tot;
    #pragma unroll
    for (int o = 1; o < 32; o <<= 1) {
        int y = __shfl_up_sync(0xffffffffu, inc, o);
        if (lane >= o) inc += y;
    }
    if (lane == 31) s_ws[wid] = inc;
    __syncthreads();
    if (wid == 0) {
        int w = (lane < 8) ? s_ws[lane] : 0;
        #pragma unroll
        for (int o = 1; o < 8; o <<= 1) {
            int y = __shfl_up_sync(0xffffffffu, w, o);
            if (lane >= o) w += y;
        }
        if (lane < 8) s_ws[lane] = w;
    }
    __syncthreads();
    int run = inc - tot + (wid ? s_ws[wid - 1] : 0);
    #pragma unroll
    for (int j = 0; j < 8; j++) { run += v[j]; s_cum[base + j] = run; }
    __syncthreads();
}

__device__ __forceinline__ float blkred(float v, float* s_fred) {
    int lane = threadIdx.x & 31, wid = threadIdx.x >> 5;
    #pragma unroll
    for (int o = 16; o; o >>= 1) v += __shfl_down_sync(0xffffffffu, v, o);
    if (lane == 0) s_fred[wid] = v;
    __syncthreads();
    float u = 0.f;
    if (wid == 0) {
        u = (lane < 8) ? s_fred[lane] : 0.f;
        #pragma unroll
        for (int o = 4; o; o >>= 1) u += __shfl_down_sync(0xffffffffu, u, o);
    }
    return u;   // valid in thread 0
}

__global__ __launch_bounds__(NT, 1) void fused_kernel(const float* __restrict__ src,
                                                      const float* __restrict__ tar,
                                                      float* __restrict__ out) {
    __shared__ int   s_buf[NBIN];       // 8KB: cum arrays / source tile (512 float4)
    __shared__ int   s_ws[8];
    __shared__ float s_fred[8];
    __shared__ int   s_up[NGRP + 1];
    float4* s_tile = (float4*)s_buf;

    int tid = threadIdx.x;
    int gid = blockIdx.x * NT + tid;

    // ---- P0: reset + fine z-histograms ----
    if (gid == 0) g_nfail = 0;
    for (int i = gid; i < NTAR; i += GTH) { g_pmk[i] = INF_KEY; g_resF[i] = 0.f; }
    for (int i = gid; i < NTOT; i += GTH) {
        if (i < NSRC) atomicAdd(&g_histS[finebin(src[3 * i + 2])], 1);
        else          atomicAdd(&g_histT[finebin(tar[3 * (i - NSRC) + 2])], 1);
    }
    gbar();

    // ---- P1 (block 0): quantile boundaries, LUT, slab offsets ----
    if (blockIdx.x == 0) {
        scan2048(g_histS, s_buf, s_ws);
        if (tid >= 1 && tid <= NS - 1) {
            int tgt = tid * SLABQ;
            int lo = 0, hi = NBIN - 1;
            while (lo < hi) { int mid = (lo + hi) >> 1; if (s_buf[mid] >= tgt) hi = mid; else lo = mid + 1; }
            g_bndbin[tid] = lo + 1;
        }
        if (tid == 0) { g_bndbin[0] = 0; g_bndbin[NS] = NBIN; }
        __syncthreads();
        if (tid <= NS) {
            float e;
            if (tid == 0) e = -1e30f;
            else if (tid == NS) e = 1e30f;
            else e = ZMINV + (float)g_bndbin[tid] * BINW;
            g_edgeZ[tid] = e;
        }
        if (tid == 0) {
            int run = 0;
            for (int k = 0; k < NS; k++) {
                g_soff[k] = run; g_sfill[k] = run;
                run = s_buf[g_bndbin[k + 1] - 1];
            }
            g_soff[NS] = run;
        }
        for (int b = tid; b < NBIN; b += NT) {
            int s = 0;
            #pragma unroll
            for (int k = 1; k < NS; k++) s += (g_bndbin[k] <= b) ? 1 : 0;
            g_lut[b] = s;
            g_histS[b] = 0;                       // reset for next replay
        }
        __syncthreads();
        scan2048(g_histT, s_buf, s_ws);
        if (tid == 0) {
            int run = 0;
            for (int k = 0; k < NS; k++) {
                g_toff[k] = run; g_tfill[k] = run;
                run = s_buf[g_bndbin[k + 1] - 1];
            }
            g_toff[NS] = run;
        }
        for (int b = tid; b < NBIN; b += NT) g_histT[b] = 0;
    }
    gbar();

    // ---- P2: counting-sort scatter (order within slab racy; min is invariant) ----
    for (int i = gid; i < NTOT; i += GTH) {
        if (i < NSRC) {
            float x = src[3 * i], y = src[3 * i + 1], z = src[3 * i + 2];
            int pos = atomicAdd(&g_sfill[g_lut[finebin(z)]], 1);
            float w = x * x + y * y + z * z;
            float4* p = (float4*)g_s8;
            p[2 * pos]     = make_float4(x, x, y, y);
            p[2 * pos + 1] = make_float4(z, z, w, w);
        } else {
            int t = i - NSRC;
            float x = tar[3 * t], y = tar[3 * t + 1], z = tar[3 * t + 2];
            int pos = atomicAdd(&g_tfill[g_lut[finebin(z)]], 1);
            g_t4[pos] = make_float4(x, y, z, x * x + y * y + z * z);
        }
    }
    gbar();

    // ---- P3 (block 0, warp 0): per-group windows + unit prefix ----
    if (blockIdx.x == 0 && tid < 32) {
        if (tid < NGRP) {
            int j0 = tid * TPG;
            int j1 = min(j0 + TPG, NTAR) - 1;
            int sf = g_lut[finebin(g_t4[j0].z)];
            int sl = g_lut[finebin(g_t4[j1].z)];
            int lo = max(sf - 1, 0), hi = min(sl + 1, NS - 1);
            g_gw[tid][0] = g_soff[lo];
            g_gw[tid][1] = g_soff[hi + 1];
            g_gz[tid][0] = g_edgeZ[lo];
            g_gz[tid][1] = g_edgeZ[hi + 1];
        }
        __syncwarp();
        if (tid == 0) {
            int run = 0;
            for (int g = 0; g < NGRP; g++) {
                g_upref[g] = run;
                run += (g_gw[g][1] - g_gw[g][0] + TILE - 1) / TILE;
            }
            g_upref[NGRP] = run;
        }
    }
    gbar();

    // ---- P4: windowed pairwise min (FFMA2 inner loop at the fp32 floor) ----
    if (tid <= NGRP) s_up[tid] = g_upref[tid];
    __syncthreads();
    int U = s_up[NGRP];
    for (int u = blockIdx.x; u < U; u += NBLK) {
        int g = 0;
        while (u >= s_up[g + 1]) g++;
        int ti = u - s_up[g];
        int s0 = g_gw[g][0] + ti * TILE;
        int cnt = min(TILE, g_gw[g][1] - s0);

        unsigned long long txp[2], typ[2], tzp[2];
        int tb = g * TPG + tid;
        #pragma unroll
        for (int h = 0; h < 2; h++) {
            int t0 = tb + (2 * h) * NT, t1 = t0 + NT;
            float ax = 0.f, ay = 0.f, az = 0.f, bx = 0.f, by = 0.f, bz = 0.f;
            if (t0 < NTAR) { float4 q = g_t4[t0]; ax = -2.f * q.x; ay = -2.f * q.y; az = -2.f * q.z; }
            if (t1 < NTAR) { float4 q = g_t4[t1]; bx = -2.f * q.x; by = -2.f * q.y; bz = -2.f * q.z; }
            txp[h] = pk(ax, bx); typ[h] = pk(ay, by); tzp[h] = pk(az, bz);
        }
        __syncthreads();
        {
            const float4* gs = (const float4*)g_s8 + 2 * s0;
            for (int idx = tid; idx < 2 * cnt; idx += NT) s_tile[idx] = gs[idx];
        }
        __syncthreads();

        float m0 = FLT_BIG, m1 = FLT_BIG, m2 = FLT_BIG, m3 = FLT_BIG;
        const ulonglong2* st = (const ulonglong2*)s_buf;
        #pragma unroll 4
        for (int j = 0; j < cnt; j++) {
            ulonglong2 q = st[2 * j];       // (x,x),(y,y)
            ulonglong2 r = st[2 * j + 1];   // (z,z),(w,w)
            F2U v0 = fma2(q.x, txp[0], r.y);
            F2U v1 = fma2(q.x, txp[1], r.y);
            v0 = fma2(q.y, typ[0], v0.u);
            v1 = fma2(q.y, typ[1], v1.u);
            v0 = fma2(r.x, tzp[0], v0.u);
            v1 = fma2(r.x, tzp[1], v1.u);
            m0 = fminf(m0, v0.f.x);
            m1 = fminf(m1, v0.f.y);
            m2 = fminf(m2, v1.f.x);
            m3 = fminf(m3, v1.f.y);
        }
        if (tb < NTAR)          atomicMin(&g_pmk[tb],          fkey(m0));
        if (tb + NT < NTAR)     atomicMin(&g_pmk[tb + NT],     fkey(m1));
        if (tb + 2 * NT < NTAR) atomicMin(&g_pmk[tb + 2 * NT], fkey(m2));
        if (tb + 3 * NT < NTAR) atomicMin(&g_pmk[tb + 3 * NT], fkey(m3));
    }
    gbar();

    // ---- P5: margin check; accumulate exact results, list failures ----
    {
        float acc = 0.f;
        for (int j = gid; j < NTAR; j += GTH) {
            int g = j / TPG;
            float4 t = g_t4[j];
            float d2 = fdec(g_pmk[j]) + t.w;            // min ||s-t||^2 over window
            float mm = fminf(t.z - g_gz[g][0], g_gz[g][1] - t.z);
            if (d2 <= mm * mm) acc += d2;               // provably exact
            else { int slot = atomicAdd(&g_nfail, 1); g_flist[slot] = j; }
        }
        float b = blkred(acc, s_fred);
        if (tid == 0) g_bsum[blockIdx.x] = b;
    }
    gbar();

    // ---- P6: fallback — tiled brute force for failed targets ----
    int nf = g_nfail;
    {
        int fgroups = (nf + NT - 1) / NT;
        int U2 = fgroups * NST;
        for (int u = blockIdx.x; u < U2; u += NBLK) {
            int fg = u / NST, ti = u % NST;
            int fidx = fg * NT + tid;
            float tx2 = 0.f, ty2 = 0.f, tz2 = 0.f;
            int j = -1;
            if (fidx < nf) {
                j = g_flist[fidx];
                float4 t = g_t4[j];
                tx2 = -2.f * t.x; ty2 = -2.f * t.y; tz2 = -2.f * t.z;
            }
            int s0 = ti * TILE;
            int cnt = min(TILE, NSRC - s0);
            __syncthreads();
            {
                const float4* gs = (const float4*)g_s8 + 2 * s0;
                for (int idx = tid; idx < 2 * cnt; idx += NT) s_tile[idx] = gs[idx];
            }
            __syncthreads();
            float best = FLT_BIG;
            #pragma unroll 4
            for (int jj = 0; jj < cnt; jj++) {
                float4 a = s_tile[2 * jj];       // (x,x,y,y)
                float4 b4 = s_tile[2 * jj + 1];  // (z,z,w,w)
                float v = fmaf(a.x, tx2, fmaf(a.z, ty2, fmaf(b4.x, tz2, b4.z)));
                best = fminf(best, v);
            }
            if (j >= 0) atomicMin(&g_pmk[j], fkey(best));
        }
    }
    gbar();

    // ---- P7: fallback contribs to fixed slots ----
    for (int f = gid; f < nf; f += GTH) {
        int j = g_flist[f];
        g_resF[j] = fdec(g_pmk[j]) + g_t4[j].w;
    }
    gbar();

    // ---- P8: deterministic final reduction ----
    {
        float acc2 = 0.f;
        for (int j = gid; j < NTAR; j += GTH) acc2 += g_resF[j];
        float b = blkred(acc2, s_fred);
        if (tid == 0) g_bsum2[blockIdx.x] = b;
    }
    gbar();
    if (blockIdx.x == 0 && tid < 32) {
        float v = 0.f;
        for (int i = tid; i < NBLK; i += 32) v += g_bsum[i] + g_bsum2[i];
        #pragma unroll
        for (int o = 16; o; o >>= 1) v += __shfl_down_sync(0xffffffffu, v, o);
        if (tid == 0) out[0] = 0.5f * v;
    }
}

extern "C" void kernel_launch(void* const* d_in, const int* in_sizes, int n_in,
                              void* d_out, int out_size) {
    const float* src = (const float*)d_in[0];   // [20000, 3] fp32
    const float* tar = (const float*)d_in[1];   // [20000, 3] fp32
    float* out = (float*)d_out;                 // scalar fp32

    fused_kernel<<<NBLK, NT>>>(src, tar, out);
}

// round 8
// speedup vs baseline: 3.3713x; 1.0055x over previous
#include <cuda_runtime.h>

#define NSRC 20000
#define NTAR 20000
#define NTOT (NSRC + NTAR)
#define NBLK 148
#define NT   512
#define GTH  (NBLK * NT)
#define CHUNKSZ ((NTOT + NBLK - 1) / NBLK)   // 271 (< NT: one point per thread)
#define NBIN 2048
#define ZMINV (-4.0f)
#define BINW (8.0f / NBIN)
#define INVBINW (NBIN / 8.0f)
#define NS   16
#define SLABQ (NSRC / NS)                  // 1250
#define TPL  2
#define TPG  (NT * TPL)                    // 1024 targets per group
#define NGRP ((NTAR + TPG - 1) / TPG)      // 20
#define TILE 256
#define NST  ((NSRC + TILE - 1) / TILE)    // 79
#define FLT_BIG 3.402823466e38f
#define INF_KEY 0x7F800000

// ---- device-global scratch (no allocation allowed) ----
__device__ int    g_histS[NBIN];
__device__ int    g_histT[NBIN];
__device__ int    g_lut[NBIN];            // fine bin -> slab
__device__ int    g_fill[2 * NS];         // scatter cursors: [0,16)=src, [16,32)=tar
__device__ float  g_s8[NSRC * 8];         // slab-sorted packed {x,x,y,y,z,z,w,w}
__device__ float4 g_t4[NTAR];             // slab-sorted targets {x,y,z,||t||^2}
__device__ int    g_pmk[NTAR];            // per-sorted-target min key
__device__ int    g_gw[NGRP][2];          // per-group src window [beg,end)
__device__ float  g_gz[NGRP][2];          // per-group window z-edges
__device__ int    g_upref[NGRP + 1];      // tile-unit prefix
__device__ int    g_nfail;
__device__ int    g_flist[NTAR];
__device__ float  g_bsum[NBLK];
__device__ unsigned          g_bar_cnt;
__device__ volatile unsigned g_bar_gen;

union F2U { unsigned long long u; float2 f; };
__device__ __forceinline__ unsigned long long pk(float lo, float hi) {
    F2U t; t.f = make_float2(lo, hi); return t.u;
}
__device__ __forceinline__ F2U fma2(unsigned long long a, unsigned long long b,
                                    unsigned long long c) {
    F2U d;
    asm("fma.rn.f32x2 %0, %1, %2, %3;" : "=l"(d.u) : "l"(a), "l"(b), "l"(c));
    return d;
}
__device__ __forceinline__ int fkey(float f) {
    int b = __float_as_int(f);
    return b >= 0 ? b : (b ^ 0x7FFFFFFF);
}
__device__ __forceinline__ float fdec(int k) {
    return __int_as_float(k >= 0 ? k : (k ^ 0x7FFFFFFF));
}
__device__ __forceinline__ int finebin(float z) {
    int b = (int)floorf((z - ZMINV) * INVBINW);
    return min(max(b, 0), NBIN - 1);
}

// Grid barrier: 148 blocks, 1/SM, all resident -> spinning is safe.
__device__ __forceinline__ void gbar() {
    __threadfence();
    __syncthreads();
    if (threadIdx.x == 0) {
        unsigned gen = g_bar_gen;
        if (atomicAdd(&g_bar_cnt, 1u) == NBLK - 1) {
            g_bar_cnt = 0;
            __threadfence();
            g_bar_gen = gen + 1;
        } else {
            while (g_bar_gen == gen) __nanosleep(32);
            __threadfence();
        }
    }
    __syncthreads();
}

// Block-0 inclusive scan of a 2048-bin histogram into s_cum (512 thr x 4 bins).
__device__ void scan2048(const int* hist, int* s_cum, int* s_ws) {
    int tid = threadIdx.x;
    int base = tid * 4;
    int4 q = *(const int4*)&hist[base];
    int tot = q.x + q.y + q.z + q.w;
    int lane = tid & 31, wid = tid >> 5;
    int inc = tot;
    #pragma unroll
    for (int o = 1; o < 32; o <<= 1) {
        int y = __shfl_up_sync(0xffffffffu, inc, o);
        if (lane >= o) inc += y;
    }
    if (lane == 31) s_ws[wid] = inc;
    __syncthreads();
    if (wid == 0) {
        int w = (lane < 16) ? s_ws[lane] : 0;
        #pragma unroll
        for (int o = 1; o < 16; o <<= 1) {
            int y = __shfl_up_sync(0xffffffffu, w, o);
            if (lane >= o) w += y;
        }
        if (lane < 16) s_ws[lane] = w;
    }
    __syncthreads();
    int run = inc - tot + (wid ? s_ws[wid - 1] : 0);
    run += q.x; s_cum[base]     = run;
    run += q.y; s_cum[base + 1] = run;
    run += q.z; s_cum[base + 2] = run;
    run += q.w; s_cum[base + 3] = run;
    __syncthreads();
}

__device__ __forceinline__ float blkred(float v, float* s_fred) {
    int lane = threadIdx.x & 31, wid = threadIdx.x >> 5;
    #pragma unroll
    for (int o = 16; o; o >>= 1) v += __shfl_down_sync(0xffffffffu, v, o);
    if (lane == 0) s_fred[wid] = v;
    __syncthreads();
    float u = 0.f;
    if (wid == 0) {
        u = (lane < 16) ? s_fred[lane] : 0.f;
        #pragma unroll
        for (int o = 8; o; o >>= 1) u += __shfl_down_sync(0xffffffffu, u, o);
    }
    return u;   // valid in thread 0
}

__global__ __launch_bounds__(NT, 1) void fused_kernel(const float* __restrict__ src,
                                                      const float* __restrict__ tar,
                                                      float* __restrict__ out) {
    __shared__ int   s_buf[NBIN];        // 8KB: scan cum / source tile (512 float4)
    __shared__ int   s_ws[16];
    __shared__ float s_fred[16];
    __shared__ int   s_bnd[NS + 1];
    __shared__ int   s_soff[NS + 1];
    __shared__ int   s_toff[NS + 1];
    __shared__ float s_edge[NS + 1];
    __shared__ int   s_up[NGRP + 1];
    __shared__ int   s_hcnt[2 * NS];
    __shared__ int   s_hbase[2 * NS];
    float4* s_tile = (float4*)s_buf;

    int tid = threadIdx.x;
    int gid = blockIdx.x * NT + tid;

    // ---- P0: reset + fine z-histograms ----
    if (gid == 0) g_nfail = 0;
    for (int i = gid; i < NTAR; i += GTH) g_pmk[i] = INF_KEY;
    for (int i = gid; i < NTOT; i += GTH) {
        if (i < NSRC) atomicAdd(&g_histS[finebin(src[3 * i + 2])], 1);
        else          atomicAdd(&g_histT[finebin(tar[3 * (i - NSRC) + 2])], 1);
    }
    gbar();

    // ---- P1 (block 0): quantiles, LUT, slab offsets, fills, windows ----
    if (blockIdx.x == 0) {
        scan2048(g_histS, s_buf, s_ws);
        if (tid >= 1 && tid < NS) {
            int tgt = tid * SLABQ;
            int lo = 0, hi = NBIN - 1;
            while (lo < hi) { int mid = (lo + hi) >> 1; if (s_buf[mid] >= tgt) hi = mid; else lo = mid + 1; }
            s_bnd[tid] = lo + 1;
        }
        if (tid == 0) { s_bnd[0] = 0; s_bnd[NS] = NBIN; }
        __syncthreads();
        if (tid <= NS) {
            s_soff[tid] = (tid == 0) ? 0 : s_buf[s_bnd[tid] - 1];
            s_edge[tid] = (tid == 0) ? -1e30f :
                          (tid == NS) ? 1e30f : (ZMINV + (float)s_bnd[tid] * BINW);
        }
        __syncthreads();
        for (int b = tid; b < NBIN; b += NT) {
            int s = 0;
            #pragma unroll
            for (int k = 1; k < NS; k++) s += (s_bnd[k] <= b) ? 1 : 0;
            g_lut[b] = s;
            g_histS[b] = 0;                        // reset for next replay
        }
        __syncthreads();
        scan2048(g_histT, s_buf, s_ws);
        if (tid <= NS) s_toff[tid] = (tid == 0) ? 0 : s_buf[s_bnd[tid] - 1];
        for (int b = tid; b < NBIN; b += NT) g_histT[b] = 0;
        __syncthreads();
        if (tid < NS) {                            // scatter cursors
            g_fill[tid]      = s_soff[tid];
            g_fill[NS + tid] = s_toff[tid];
        }
        if (tid < NGRP) {                          // windows from target RANKS
            int j0 = tid * TPG;
            int j1 = min(j0 + TPG, NTAR) - 1;
            int sf = 0, sl = 0;
            #pragma unroll
            for (int k = 1; k < NS; k++) {
                sf += (s_toff[k] <= j0) ? 1 : 0;
                sl += (s_toff[k] <= j1) ? 1 : 0;
            }
            int lo = max(sf - 1, 0), hi = min(sl + 1, NS - 1);
            g_gw[tid][0] = s_soff[lo];
            g_gw[tid][1] = s_soff[hi + 1];
            g_gz[tid][0] = s_edge[lo];
            g_gz[tid][1] = s_edge[hi + 1];
        }
        __syncthreads();
        if (tid == 0) {
            int run = 0;
            for (int g = 0; g < NGRP; g++) {
                g_upref[g] = run;
                run += (g_gw[g][1] - g_gw[g][0] + TILE - 1) / TILE;
            }
            g_upref[NGRP] = run;
        }
    }
    gbar();

    // ---- P2: block-aggregated counting-sort scatter ----
    // One global atomic per (block, slab) instead of per point.
    {
        int i = blockIdx.x * CHUNKSZ + tid;
        bool valid = (tid < CHUNKSZ) && (i < NTOT);
        int slab = 0;
        float x = 0.f, y = 0.f, z = 0.f;
        if (valid) {
            if (i < NSRC) {
                x = src[3 * i]; y = src[3 * i + 1]; z = src[3 * i + 2];
                slab = g_lut[finebin(z)];
            } else {
                int t = i - NSRC;
                x = tar[3 * t]; y = tar[3 * t + 1]; z = tar[3 * t + 2];
                slab = NS + g_lut[finebin(z)];
            }
        }
        if (tid < 2 * NS) s_hcnt[tid] = 0;
        __syncthreads();
        int lpos = 0;
        if (valid) lpos = atomicAdd(&s_hcnt[slab], 1);
        __syncthreads();
        if (tid < 2 * NS && s_hcnt[tid] > 0)
            s_hbase[tid] = atomicAdd(&g_fill[tid], s_hcnt[tid]);
        __syncthreads();
        if (valid) {
            int pos = s_hbase[slab] + lpos;
            float w = x * x + y * y + z * z;
            if (i < NSRC) {
                float4* p = (float4*)g_s8;
                p[2 * pos]     = make_float4(x, x, y, y);
                p[2 * pos + 1] = make_float4(z, z, w, w);
            } else {
                g_t4[pos] = make_float4(x, y, z, w);
            }
        }
    }
    gbar();

    // ---- P4: windowed pairwise min (FFMA2 loop at the fp32 floor) ----
    if (tid <= NGRP) s_up[tid] = g_upref[tid];
    __syncthreads();
    int U = s_up[NGRP];
    for (int u = blockIdx.x; u < U; u += NBLK) {
        int g = 0;
        while (u >= s_up[g + 1]) g++;
        int ti = u - s_up[g];
        int s0 = g_gw[g][0] + ti * TILE;
        int cnt = min(TILE, g_gw[g][1] - s0);

        int tb = g * TPG + tid;
        int t1i = tb + NT;
        float ax = 0.f, ay = 0.f, az = 0.f, bx = 0.f, by = 0.f, bz = 0.f;
        if (tb < NTAR)  { float4 q = g_t4[tb];  ax = -2.f * q.x; ay = -2.f * q.y; az = -2.f * q.z; }
        if (t1i < NTAR) { float4 q = g_t4[t1i]; bx = -2.f * q.x; by = -2.f * q.y; bz = -2.f * q.z; }
        unsigned long long txp = pk(ax, bx), typ = pk(ay, by), tzp = pk(az, bz);

        __syncthreads();
        {
            const float4* gs = (const float4*)g_s8 + 2 * s0;
            for (int idx = tid; idx < 2 * cnt; idx += NT) s_tile[idx] = gs[idx];
        }
        __syncthreads();

        float m0 = FLT_BIG, m1 = FLT_BIG;
        const ulonglong2* st = (const ulonglong2*)s_buf;
        #pragma unroll 4
        for (int j = 0; j < cnt; j++) {
            ulonglong2 q = st[2 * j];       // (x,x),(y,y)
            ulonglong2 r = st[2 * j + 1];   // (z,z),(w,w)
            F2U v = fma2(q.x, txp, r.y);
            v = fma2(q.y, typ, v.u);
            v = fma2(r.x, tzp, v.u);
            m0 = fminf(m0, v.f.x);
            m1 = fminf(m1, v.f.y);
        }
        if (tb < NTAR)  atomicMin(&g_pmk[tb],  fkey(m0));
        if (t1i < NTAR) atomicMin(&g_pmk[t1i], fkey(m1));
    }
    gbar();

    // ---- P5: margin check — list provably-inexact targets ----
    for (int j = gid; j < NTAR; j += GTH) {
        int g = j / TPG;
        float4 t = g_t4[j];
        float d2 = fdec(g_pmk[j]) + t.w;             // min ||s-t||^2 over window
        float mm = fminf(t.z - g_gz[g][0], g_gz[g][1] - t.z);
        if (!(d2 <= mm * mm)) {
            int slot = atomicAdd(&g_nfail, 1);
            g_flist[slot] = j;
        }
    }
    gbar();

    // ---- P6: fallback — tiled brute force for failed targets (exact) ----
    int nf = g_nfail;
    {
        int fgroups = (nf + NT - 1) / NT;
        int U2 = fgroups * NST;
        for (int u = blockIdx.x; u < U2; u += NBLK) {
            int fg = u / NST, ti = u % NST;
            int fidx = fg * NT + tid;
            float tx2 = 0.f, ty2 = 0.f, tz2 = 0.f;
            int j = -1;
            if (fidx < nf) {
                j = g_flist[fidx];
                float4 t = g_t4[j];
                tx2 = -2.f * t.x; ty2 = -2.f * t.y; tz2 = -2.f * t.z;
            }
            int s0 = ti * TILE;
            int cnt = min(TILE, NSRC - s0);
            __syncthreads();
            {
                const float4* gs = (const float4*)g_s8 + 2 * s0;
                for (int idx = tid; idx < 2 * cnt; idx += NT) s_tile[idx] = gs[idx];
            }
            __syncthreads();
            float best = FLT_BIG;
            #pragma unroll 4
            for (int jj = 0; jj < cnt; jj++) {
                float4 a  = s_tile[2 * jj];       // (x,x,y,y)
                float4 b4 = s_tile[2 * jj + 1];   // (z,z,w,w)
                float v = fmaf(a.x, tx2, fmaf(a.z, ty2, fmaf(b4.x, tz2, b4.z)));
                best = fminf(best, v);
            }
            if (j >= 0) atomicMin(&g_pmk[j], fkey(best));
        }
    }
    gbar();

    // ---- P7: final sum straight from pmk (fixed per-thread order) ----
    {
        float acc = 0.f;
        for (int j = gid; j < NTAR; j += GTH)
            acc += fdec(g_pmk[j]) + g_t4[j].w;
        float b = blkred(acc, s_fred);
        if (tid == 0) g_bsum[blockIdx.x] = b;
    }
    gbar();
    if (blockIdx.x == 0 && tid < 32) {
        float v = 0.f;
        for (int i = tid; i < NBLK; i += 32) v += g_bsum[i];
        #pragma unroll
        for (int o = 16; o; o >>= 1) v += __shfl_down_sync(0xffffffffu, v, o);
        if (tid == 0) out[0] = 0.5f * v;
    }
}

extern "C" void kernel_launch(void* const* d_in, const int* in_sizes, int n_in,
                              void* d_out, int out_size) {
    const float* src = (const float*)d_in[0];   // [20000, 3] fp32
    const float* tar = (const float*)d_in[1];   // [20000, 3] fp32
    float* out = (float*)d_out;                 // scalar fp32

    fused_kernel<<<NBLK, NT>>>(src, tar, out);
}